// round 6
// baseline (speedup 1.0000x reference)
#include <cuda_runtime.h>
#include <cuda_bf16.h>
#include <cstdint>

// GraphSage_89781996355909 — exact algebraic collapse (see R1 analysis).
//
// Final reference op: jax.nn.softmax(x @ W5 + b5, axis=-1) with last-axis
// dim 1 (W5: [8,1]). Single-element softmax == 1.0 for any finite logit, and
// all upstream values are finite, so output == ones(512) for ALL inputs.
//
// R6: winning R3 shape (1 CTA x 128 threads, 4 warps issuing STG.128 across
// all 4 SMSPs in parallel) with the bounds check removed for the known
// out_size=512 case: each thread does exactly one unpredicated 16B store.
// Generic predicated fallbacks kept for any other out_size/alignment.

__global__ void __launch_bounds__(128, 1)
GraphSage_89781996355909_fill512(float4* __restrict__ out4) {
    out4[threadIdx.x] = make_float4(1.0f, 1.0f, 1.0f, 1.0f);
}

__global__ void GraphSage_89781996355909_fill4(float4* __restrict__ out4, int n4) {
    int i = threadIdx.x + blockIdx.x * blockDim.x;
    if (i < n4) out4[i] = make_float4(1.0f, 1.0f, 1.0f, 1.0f);
}

__global__ void GraphSage_89781996355909_fill1(float* __restrict__ out, int n) {
    int i = threadIdx.x + blockIdx.x * blockDim.x;
    if (i < n) out[i] = 1.0f;
}

extern "C" void kernel_launch(void* const* d_in, const int* in_sizes, int n_in,
                              void* d_out, int out_size) {
    (void)d_in; (void)in_sizes; (void)n_in;
    bool aligned16 = (((unsigned long long)d_out) & 15ull) == 0;
    if (out_size == 512 && aligned16) {
        GraphSage_89781996355909_fill512<<<1, 128>>>((float4*)d_out);
    } else if ((out_size & 3) == 0 && aligned16) {
        int n4 = out_size >> 2;
        int threads = (n4 < 128) ? (n4 > 0 ? n4 : 1) : 128;
        int blocks = (n4 + threads - 1) / threads;
        if (blocks < 1) blocks = 1;
        GraphSage_89781996355909_fill4<<<blocks, threads>>>((float4*)d_out, n4);
    } else {
        int threads = 256;
        int blocks = (out_size + threads - 1) / threads;
        if (blocks < 1) blocks = 1;
        GraphSage_89781996355909_fill1<<<blocks, threads>>>((float*)d_out, out_size);
    }
}